// round 11
// baseline (speedup 1.0000x reference)
#include <cuda_runtime.h>
#include <cuda_bf16.h>
#include <cstdint>

#define LG 6
#define TSZ 524288
#define TMASK 0x7FFFFu
#define MPTS 64
#define NTHR 256
#define W0S 5.0f
#define W0H 10.0f

// smem byte map
#define SM_XHI 0            // bf16 x_hi [64][256], swizzled, 32KB
#define SM_XLO 32768        // bf16 x_lo, 32KB
#define SM_W   65536        // 2 x (32KB Whi + 32KB Wlo) phase buffers
#define SM_SG  196608       // float[64*12]
#define SM_SP  199680       // float[64*3]
#define SMEM_BYTES 200448

// [g][split][phase][n=256][128B swizzled row] ; g = layer*2 + (0=Ws,1=Wh)
__device__ __align__(128) unsigned char g_wscratch[12 * 2 * 4 * 32768];

// ---------------- helpers ----------------
static __device__ __forceinline__ uint32_t smem_u32(const void* p) {
    uint32_t a;
    asm("{ .reg .u64 t; cvta.to.shared.u64 t, %1; cvt.u32.u64 %0, t; }" : "=r"(a) : "l"(p));
    return a;
}
static __device__ __forceinline__ void cp16(uint32_t s, const void* g) {
    asm volatile("cp.async.cg.shared.global [%0], [%1], 16;" :: "r"(s), "l"(g));
}
static __device__ __forceinline__ void cp_commit() {
    asm volatile("cp.async.commit_group;" ::: "memory");
}
static __device__ __forceinline__ void cp_wait0() {
    asm volatile("cp.async.wait_group 0;" ::: "memory");
}
#define LDM4(r, addr) \
    asm volatile("ldmatrix.sync.aligned.m8n8.x4.shared.b16 {%0,%1,%2,%3}, [%4];" \
        : "=r"((r)[0]), "=r"((r)[1]), "=r"((r)[2]), "=r"((r)[3]) : "r"(addr))

static __device__ __forceinline__ void mma16816(float* d, const uint32_t* a,
                                                uint32_t b0, uint32_t b1) {
    asm volatile(
        "mma.sync.aligned.m16n8k16.row.col.f32.bf16.bf16.f32 "
        "{%0,%1,%2,%3}, {%4,%5,%6,%7}, {%8,%9}, {%0,%1,%2,%3};"
        : "+f"(d[0]), "+f"(d[1]), "+f"(d[2]), "+f"(d[3])
        : "r"(a[0]), "r"(a[1]), "r"(a[2]), "r"(a[3]), "r"(b0), "r"(b1));
}

// write one (row, d0..d0+1) pair into swizzled x_hi / x_lo tiles
static __device__ __forceinline__ void store_x(char* sb, int row, int d0, float va, float vb) {
    const int unit = (d0 >> 3) & 7;
    const int byte = row * 512 + ((d0 >> 6) << 7) + ((unit ^ (row & 7)) << 4) + (d0 & 7) * 2;
    const __nv_bfloat16 ha = __float2bfloat16(va), hb = __float2bfloat16(vb);
    const __nv_bfloat16 la = __float2bfloat16(va - __bfloat162float(ha));
    const __nv_bfloat16 lb = __float2bfloat16(vb - __bfloat162float(hb));
    *(uint32_t*)(sb + SM_XHI + byte) =
        (uint32_t)__bfloat16_as_ushort(ha) | ((uint32_t)__bfloat16_as_ushort(hb) << 16);
    *(uint32_t*)(sb + SM_XLO + byte) =
        (uint32_t)__bfloat16_as_ushort(la) | ((uint32_t)__bfloat16_as_ushort(lb) << 16);
}

// ---------------- prep: split W into bf16 hi/lo, ldmatrix-B layout ----------------
// layout: base + g*262144 + split*131072 + phase*32768 + n*128 + ((u ^ (n&7))<<4)
__global__ void prep_kernel(const float* __restrict__ gWs, const float* __restrict__ gWh) {
    const int idx = blockIdx.x * blockDim.x + threadIdx.x;  // 12*8192
    const int n  = idx & 255;
    const int ku = (idx >> 8) & 31;
    const int g  = idx >> 13;
    const float* src = ((g & 1) ? gWh : gWs) + (size_t)(g >> 1) * 65536;
    const int c = ku >> 3, u = ku & 7;
    unsigned short hi8[8], lo8[8];
    #pragma unroll
    for (int j = 0; j < 8; j++) {
        const int k = c * 64 + u * 8 + j;
        const float w = __ldg(&src[k * 256 + n]);
        const __nv_bfloat16 h = __float2bfloat16(w);
        const __nv_bfloat16 l = __float2bfloat16(w - __bfloat162float(h));
        hi8[j] = __bfloat16_as_ushort(h);
        lo8[j] = __bfloat16_as_ushort(l);
    }
    const size_t off = (size_t)c * 32768 + n * 128 + ((u ^ (n & 7)) << 4);
    unsigned char* bp = g_wscratch + (size_t)g * 262144;
    *(uint4*)(bp + off)          = *(uint4*)hi8;
    *(uint4*)(bp + 131072 + off) = *(uint4*)lo8;
}

// ---------------- main fused kernel ----------------
__global__ void __launch_bounds__(NTHR, 1)
ffb_kernel(const float* __restrict__ gpos,
           const float* __restrict__ gtable,
           const float* __restrict__ gA,
           const float* __restrict__ gW0,
           const float* __restrict__ gb0,
           const float* __restrict__ gbs,
           const float* __restrict__ gbh,
           float* __restrict__ gout)
{
    extern __shared__ float sf[];
    char* sb = (char*)sf;
    const uint32_t su = smem_u32(sf);
    const int tid = threadIdx.x, wid = tid >> 5, lane = tid & 31;
    const int base = blockIdx.x * MPTS;
    float* sg  = sf + SM_SG / 4;
    float* spp = sf + SM_SP / 4;

    // continuous weight pipeline: global phase gp = g*4 + p, buffer = gp & 1
    auto copy_phase = [&](int gp) {
        const uint32_t dst = su + SM_W + (uint32_t)(gp & 1) * 65536 + tid * 16;
        const unsigned char* src = g_wscratch + (size_t)(gp >> 2) * 262144
                                 + (size_t)(gp & 3) * 32768 + tid * 16;
        #pragma unroll
        for (int q = 0; q < 8; q++) {
            cp16(dst + q * 4096, src + q * 4096);
            cp16(dst + 32768 + q * 4096, src + 131072 + q * 4096);
        }
        cp_commit();
    };
    int gpc = 0;                 // next phase to copy
    copy_phase(gpc++);           // gemm 0 phase 0 streams under grid encode

    for (int i = tid; i < MPTS * 3; i += NTHR) spp[i] = gpos[(size_t)base * 3 + i];
    __syncthreads();

    // ---- hash grid: 64 pts x 6 levels ----
    for (int t = tid; t < MPTS * LG; t += NTHR) {
        const int m = t / LG, l = t % LG;
        const float scale = (float)(16 << l);
        const float px = (spp[m * 3 + 0] + 1.0f) * 0.5f * scale;
        const float py = (spp[m * 3 + 1] + 1.0f) * 0.5f * scale;
        const float pz = (spp[m * 3 + 2] + 1.0f) * 0.5f * scale;
        const float fx = floorf(px), fy = floorf(py), fz = floorf(pz);
        const float rx = px - fx, ry = py - fy, rz = pz - fz;
        const unsigned ix = (unsigned)(int)fx, iy = (unsigned)(int)fy, iz = (unsigned)(int)fz;
        const float2* tbl = (const float2*)gtable + (size_t)l * TSZ;
        float g0 = 0.0f, g1 = 0.0f;
        #pragma unroll
        for (int c = 0; c < 8; ++c) {
            const unsigned bi = (c >> 2) & 1u, bj = (c >> 1) & 1u, bk = c & 1u;
            const unsigned h = ((ix + bi) ^ ((iy + bj) * 2654435761u)
                              ^ ((iz + bk) * 805459861u)) & TMASK;
            const float2 f = __ldg(&tbl[h]);
            const float w = (bi ? rx : 1.0f - rx) * (bj ? ry : 1.0f - ry) * (bk ? rz : 1.0f - rz);
            g0 = fmaf(w, f.x, g0);
            g1 = fmaf(w, f.y, g1);
        }
        sg[m * 12 + l * 2 + 0] = g0;
        sg[m * 12 + l * 2 + 1] = g1;
    }
    __syncthreads();

    // warp tiling: 4 m-strips (16 rows) x 2 n-halves (128 cols)
    const int ms = wid & 3, nh = wid >> 2;
    const int m0 = ms * 16, ncol0 = nh * 128;
    const int rowA = m0 + (lane & 15);
    const int aku  = lane >> 4;
    const int r1 = m0 + (lane >> 2), r2 = r1 + 8;
    const int dq = (lane & 3) * 2;
    const int nB = (lane & 7) + ((lane >> 4) << 3);
    const int uB = (lane >> 3) & 1;

    // ---- layer 0: x = sin(5*(pos@W0+b0)) -> x tiles ----
    {
        const float px1 = spp[r1 * 3], py1 = spp[r1 * 3 + 1], pz1 = spp[r1 * 3 + 2];
        const float px2 = spp[r2 * 3], py2 = spp[r2 * 3 + 1], pz2 = spp[r2 * 3 + 2];
        #pragma unroll
        for (int nt = 0; nt < 16; nt++) {
            const int d0 = ncol0 + nt * 8 + dq;
            const float2 w0 = __ldg((const float2*)(gW0 + d0));
            const float2 w1 = __ldg((const float2*)(gW0 + 256 + d0));
            const float2 w2 = __ldg((const float2*)(gW0 + 512 + d0));
            const float2 bb = __ldg((const float2*)(gb0 + d0));
            const float v00 = __sinf(W0S * fmaf(px1, w0.x, fmaf(py1, w1.x, fmaf(pz1, w2.x, bb.x))));
            const float v01 = __sinf(W0S * fmaf(px1, w0.y, fmaf(py1, w1.y, fmaf(pz1, w2.y, bb.y))));
            const float v10 = __sinf(W0S * fmaf(px2, w0.x, fmaf(py2, w1.x, fmaf(pz2, w2.x, bb.x))));
            const float v11 = __sinf(W0S * fmaf(px2, w0.y, fmaf(py2, w1.y, fmaf(pz2, w2.y, bb.y))));
            store_x(sb, r1, d0, v00, v01);
            store_x(sb, r2, d0, v10, v11);
        }
    }

    float acc[16][4];
    float oacc[16][4];
    #pragma unroll
    for (int i = 0; i < 16; i++)
        #pragma unroll
        for (int q = 0; q < 4; q++) oacc[i][q] = 0.0f;

    // GEMM: acc = x @ W[g]  (3-term bf16 split, fp32 accum)
    // weight copies ride the continuous pipeline: copy(gp+1) issued at top of gp
    auto do_gemm = [&]() {
        #pragma unroll
        for (int i = 0; i < 16; i++)
            #pragma unroll
            for (int q = 0; q < 4; q++) acc[i][q] = 0.0f;
        #pragma unroll 1
        for (int p = 0; p < 4; p++) {
            cp_wait0();
            __syncthreads();
            if (gpc < 48) copy_phase(gpc++);
            const uint32_t wb = su + SM_W + (p & 1) * 65536;
            #pragma unroll
            for (int ks = 0; ks < 4; ks++) {
                uint32_t ahi[4], alo[4];
                const uint32_t ax = (uint32_t)(rowA * 512 + p * 128
                                  + ((((ks << 1) + aku) ^ (rowA & 7)) << 4));
                LDM4(ahi, su + SM_XHI + ax);
                LDM4(alo, su + SM_XLO + ax);
                const uint32_t bsw = ((((ks << 1) + uB) ^ (lane & 7)) << 4);
                #pragma unroll
                for (int np = 0; np < 8; np++) {
                    uint32_t bh[4], bl[4];
                    const uint32_t bo = (uint32_t)((ncol0 + nB + np * 16) * 128) + bsw;
                    LDM4(bh, wb + bo);
                    LDM4(bl, wb + 32768 + bo);
                    mma16816(acc[np * 2],     ahi, bh[0], bh[1]);
                    mma16816(acc[np * 2 + 1], ahi, bh[2], bh[3]);
                    mma16816(acc[np * 2],     alo, bh[0], bh[1]);
                    mma16816(acc[np * 2 + 1], alo, bh[2], bh[3]);
                    mma16816(acc[np * 2],     ahi, bl[0], bl[1]);
                    mma16816(acc[np * 2 + 1], ahi, bl[2], bl[3]);
                }
            }
        }
        __syncthreads();
    };

    #pragma unroll 1
    for (int layer = 0; layer < LG; layer++) {
        // ===== z = x @ Ws =====
        do_gemm();
        // ---- epilogue 1: x = sin(5(z+bs)) + sin(sig*(g@A)) ----
        {
            const float g01 = sg[r1 * 12 + layer * 2], g11 = sg[r1 * 12 + layer * 2 + 1];
            const float g02 = sg[r2 * 12 + layer * 2], g12 = sg[r2 * 12 + layer * 2 + 1];
            const float s2 = 6.283185307179586f * (5.0f * (float)(1 << layer));
            #pragma unroll
            for (int nt = 0; nt < 16; nt++) {
                const int d0 = ncol0 + nt * 8 + dq;
                const float2 bs = __ldg((const float2*)(gbs + layer * 256 + d0));
                const float2 a0 = __ldg((const float2*)(gA + layer * 512 + d0));
                const float2 a1 = __ldg((const float2*)(gA + layer * 512 + 256 + d0));
                const float v00 = __sinf(W0S * (acc[nt][0] + bs.x))
                                + __sinf(s2 * fmaf(g01, a0.x, g11 * a1.x));
                const float v01 = __sinf(W0S * (acc[nt][1] + bs.y))
                                + __sinf(s2 * fmaf(g01, a0.y, g11 * a1.y));
                const float v10 = __sinf(W0S * (acc[nt][2] + bs.x))
                                + __sinf(s2 * fmaf(g02, a0.x, g12 * a1.x));
                const float v11 = __sinf(W0S * (acc[nt][3] + bs.y))
                                + __sinf(s2 * fmaf(g02, a0.y, g12 * a1.y));
                store_x(sb, r1, d0, v00, v01);
                store_x(sb, r2, d0, v10, v11);
            }
        }
        // ===== z2 = x @ Wh =====
        do_gemm();
        // ---- epilogue 2: out += sin(10(z2+bh)) (registers) ----
        {
            #pragma unroll
            for (int nt = 0; nt < 16; nt++) {
                const int d0 = ncol0 + nt * 8 + dq;
                const float2 bh = __ldg((const float2*)(gbh + layer * 256 + d0));
                oacc[nt][0] += __sinf(W0H * (acc[nt][0] + bh.x));
                oacc[nt][1] += __sinf(W0H * (acc[nt][1] + bh.y));
                oacc[nt][2] += __sinf(W0H * (acc[nt][2] + bh.x));
                oacc[nt][3] += __sinf(W0H * (acc[nt][3] + bh.y));
            }
        }
    }

    // ---- writeback ----
    #pragma unroll
    for (int nt = 0; nt < 16; nt++) {
        const int d0 = ncol0 + nt * 8 + dq;
        *(float2*)(gout + (size_t)(base + r1) * 256 + d0) = make_float2(oacc[nt][0], oacc[nt][1]);
        *(float2*)(gout + (size_t)(base + r2) * 256 + d0) = make_float2(oacc[nt][2], oacc[nt][3]);
    }
}

extern "C" void kernel_launch(void* const* d_in, const int* in_sizes, int n_in,
                              void* d_out, int out_size) {
    const float* gpos   = (const float*)d_in[0];
    const float* gtable = (const float*)d_in[1];
    const float* gA     = (const float*)d_in[2];
    const float* gW0    = (const float*)d_in[3];
    const float* gb0    = (const float*)d_in[4];
    const float* gWs    = (const float*)d_in[5];
    const float* gbs    = (const float*)d_in[6];
    const float* gWh    = (const float*)d_in[7];
    const float* gbh    = (const float*)d_in[8];
    float* gout = (float*)d_out;

    const int n = in_sizes[0] / 3;
    prep_kernel<<<384, 256>>>(gWs, gWh);
    cudaFuncSetAttribute(ffb_kernel, cudaFuncAttributeMaxDynamicSharedMemorySize, SMEM_BYTES);
    ffb_kernel<<<n / MPTS, NTHR, SMEM_BYTES>>>(gpos, gtable, gA, gW0, gb0, gbs, gbh, gout);
}